// round 1
// baseline (speedup 1.0000x reference)
#include <cuda_runtime.h>
#include <math.h>

// Problem dims (fixed by setup_inputs)
#define NB   8
#define NG   1024
#define NK   32
#define NC   168
#define NFD  56
#define NCH  336
#define GKS  (NG * NK)     // 32768

// Accumulators: [0]=sum_x [1]=sumsq_x [2]=sum_xyz [3]=sumsq_xyz
__device__ double g_acc[4];
__device__ float  g_inv[2];   // [0]=1/(std_x+eps), [1]=1/(std_xyz+eps)

// ---------------------------------------------------------------------------
// Precise-enough fast sincos: Cody-Waite reduction by 2*pi, then MUFU sin/cos.
// |x| <= ~1000 here -> reduced-angle error ~1e-7, MUFU error ~4e-7.
// ---------------------------------------------------------------------------
namespace cw {
constexpr double TWO_PI_D = 6.283185307179586476925286766559;
constexpr float  RED_A = 6.28125f;                                       // exact
constexpr float  RED_B = (float)(TWO_PI_D - (double)RED_A);
constexpr float  RED_C = (float)(TWO_PI_D - (double)RED_A - (double)RED_B);
constexpr float  INV_2PI = 0.15915494309189535f;
}

__device__ __forceinline__ void fsincos(float x, float& s, float& c) {
    float n = rintf(x * cw::INV_2PI);
    float y = fmaf(n, -cw::RED_A, x);
    y = fmaf(n, -cw::RED_B, y);
    y = fmaf(n, -cw::RED_C, y);
    s = __sinf(y);
    c = __cosf(y);
}

// log2(1000)/56
constexpr float K_LOG2A_FD = 0.17796043365468013f;

// ---------------------------------------------------------------------------
// Reduction helpers
// ---------------------------------------------------------------------------
__global__ void k_zero() {
    if (threadIdx.x < 4) g_acc[threadIdx.x] = 0.0;
}

__device__ __forceinline__ void block_reduce_add(float s, float s2, int slot) {
    double ds = (double)s, ds2 = (double)s2;
    #pragma unroll
    for (int o = 16; o; o >>= 1) {
        ds  += __shfl_down_sync(0xffffffffu, ds,  o);
        ds2 += __shfl_down_sync(0xffffffffu, ds2, o);
    }
    __shared__ double sh[2][8];
    int w = threadIdx.x >> 5;
    if ((threadIdx.x & 31) == 0) { sh[0][w] = ds; sh[1][w] = ds2; }
    __syncthreads();
    if (threadIdx.x == 0) {
        double a = 0.0, b = 0.0;
        int nw = blockDim.x >> 5;
        for (int i = 0; i < nw; i++) { a += sh[0][i]; b += sh[1][i]; }
        atomicAdd(&g_acc[slot], a);
        atomicAdd(&g_acc[slot + 1], b);
    }
}

// d = knn_x[b,g,k,c] - lc_x[b,g,c]; accumulate sum(d), sum(d^2)
__global__ void k_reduce_x(const float4* __restrict__ knn_x4,
                           const float*  __restrict__ lc_x) {
    const int N4 = NB * NG * NK * NC / 4;   // 11,010,048
    float s = 0.0f, s2 = 0.0f;
    int stride = gridDim.x * blockDim.x;
    for (int i = blockIdx.x * blockDim.x + threadIdx.x; i < N4; i += stride) {
        int e  = i * 4;
        int bg = e / (NK * NC);
        int c  = e % NC;                    // c % 4 == 0, within one row
        float4 v = knn_x4[i];
        float4 l = *(const float4*)(lc_x + bg * NC + c);
        float d0 = v.x - l.x, d1 = v.y - l.y, d2 = v.z - l.z, d3 = v.w - l.w;
        s  += (d0 + d1) + (d2 + d3);
        s2 += (d0 * d0 + d1 * d1) + (d2 * d2 + d3 * d3);
    }
    block_reduce_add(s, s2, 0);
}

__global__ void k_reduce_xyz(const float* __restrict__ knn_xyz,
                             const float* __restrict__ lc_xyz) {
    const int N = NB * NG * NK * 3;         // 786,432
    float s = 0.0f, s2 = 0.0f;
    int stride = gridDim.x * blockDim.x;
    for (int i = blockIdx.x * blockDim.x + threadIdx.x; i < N; i += stride) {
        int d  = i % 3;
        int bg = i / (NK * 3);
        float v = knn_xyz[i] - __ldg(lc_xyz + bg * 3 + d);
        s  += v;
        s2 += v * v;
    }
    block_reduce_add(s, s2, 2);
}

__global__ void k_finalize() {
    const double nx = (double)NB * NG * NK * NC;
    const double nz = (double)NB * NG * NK * 3;
    double vx = (g_acc[1] - g_acc[0] * g_acc[0] / nx) / (nx - 1.0);
    double vz = (g_acc[3] - g_acc[2] * g_acc[2] / nz) / (nz - 1.0);
    g_inv[0] = (float)(1.0 / (sqrt(vx) + 1e-5));
    g_inv[1] = (float)(1.0 / (sqrt(vz) + 1e-5));
}

// ---------------------------------------------------------------------------
// Main kernel: one block per (b,g). 256 threads.
// smem layout (floats):
//   s_pe   [336*32] : pe[c][k] (knn trig + lc trig)
//   s_knnx [32*169] : normalized knn_x tile, padded row stride 169
//   s_xn   [3*32]   : normalized knn_xyz, [dim][k]
//   s_emb  [7*32]   : {xyz_n(3), cross(3), dot} per k
//   s_lct  [336]    : lc-side trig per channel
//   s_inv  [56]     : 1/alpha^(f/56)
// ---------------------------------------------------------------------------
#define S_PE    0
#define S_KNNX  (S_PE + NCH * NK)            // 10752
#define S_XN    (S_KNNX + NK * 169)          // 16160
#define S_EMB   (S_XN + 3 * NK)              // 16256
#define S_LCT   (S_EMB + 7 * NK)             // 16480
#define S_INV   (S_LCT + NCH)                // 16816
#define SMEM_FLOATS (S_INV + NFD)            // 16872
#define SMEM_BYTES  (SMEM_FLOATS * 4)        // 67488

__global__ __launch_bounds__(256, 3)
void k_main(const float* __restrict__ lc_xyz, const float* __restrict__ lc_x,
            const float* __restrict__ knn_xyz, const float* __restrict__ knn_x,
            float* __restrict__ out) {
    extern __shared__ float sm[];
    const int bg   = blockIdx.x;             // b*NG + g
    const int t    = threadIdx.x;
    const int lane = t & 31;
    const int w    = t >> 5;

    const float inv_x = g_inv[0];
    const float inv_z = g_inv[1];

    // ---- phase 1 -----------------------------------------------------------
    if (t < NFD)
        sm[S_INV + t] = 1.0f / exp2f((float)t * K_LOG2A_FD);

    if (t < 3 * NK) {                         // normalized knn_xyz
        int d = t % 3, k = t / 3;
        float v = knn_xyz[bg * (NK * 3) + t] - __ldg(lc_xyz + bg * 3 + d);
        sm[S_XN + d * NK + k] = v * inv_z;
    }

    if (t < 3 * NFD) {                        // lc-side trig (raw lc_xyz)
        int d = t / NFD, f = t % NFD;
        float inv = 1.0f / exp2f((float)f * K_LOG2A_FD);
        float a = 100.0f * __ldg(lc_xyz + bg * 3 + d) * inv;
        float sn, cs;
        fsincos(a, sn, cs);
        sm[S_LCT + d * 112 + f]      = sn;
        sm[S_LCT + d * 112 + 56 + f] = cs;
    }

    // normalized knn_x tile (coalesced float4 loads, padded smem rows)
    {
        const float4* kx4 = (const float4*)(knn_x + (size_t)bg * NK * NC);
        for (int i = t; i < NK * NC / 4; i += 256) {
            int e = i * 4;
            int k = e / NC, c = e - k * NC;   // c % 4 == 0
            float4 v = kx4[i];
            float4 l = *(const float4*)(lc_x + bg * NC + c);
            float* dst = &sm[S_KNNX + k * 169 + c];
            dst[0] = (v.x - l.x) * inv_x;
            dst[1] = (v.y - l.y) * inv_x;
            dst[2] = (v.z - l.z) * inv_x;
            dst[3] = (v.w - l.w) * inv_x;
        }
    }
    __syncthreads();

    // ---- phase 2 -----------------------------------------------------------
    if (t < NK) {                             // 7-channel geometric embedding
        int k = t;
        float a0 = sm[S_XN + k], a1 = sm[S_XN + NK + k], a2 = sm[S_XN + 2 * NK + k];
        float b0 = __ldg(lc_xyz + bg * 3 + 0);
        float b1 = __ldg(lc_xyz + bg * 3 + 1);
        float b2 = __ldg(lc_xyz + bg * 3 + 2);
        sm[S_EMB + 0 * NK + k] = a0;
        sm[S_EMB + 1 * NK + k] = a1;
        sm[S_EMB + 2 * NK + k] = a2;
        sm[S_EMB + 3 * NK + k] = a1 * b2 - a2 * b1;
        sm[S_EMB + 4 * NK + k] = a2 * b0 - a0 * b2;
        sm[S_EMB + 5 * NK + k] = a0 * b1 - a1 * b0;
        sm[S_EMB + 6 * NK + k] = a0 * b0 + a1 * b1 + a2 * b2;
    }

    // pe fill: 3*56*32 = 5376 sincos tasks, 21 per thread; (dim,f) warp-uniform
    #pragma unroll 3
    for (int it = 0; it < 21; ++it) {
        int task = t + it * 256;
        int k  = task & 31;
        int df = task >> 5;                   // 0..167, warp-uniform
        int d  = df / NFD;
        int f  = df - d * NFD;
        float a = 100.0f * sm[S_XN + d * NK + k] * sm[S_INV + f];
        float sn, cs;
        fsincos(a, sn, cs);
        int cb = d * 112 + f;
        sm[S_PE + cb * NK + k]        = sn + sm[S_LCT + cb];
        sm[S_PE + (cb + 56) * NK + k] = cs + sm[S_LCT + cb + 56];
    }
    __syncthreads();

    // ---- phase 3: write output --------------------------------------------
    const int b = bg >> 10;                   // bg / NG
    const int g = bg & (NG - 1);
    const size_t obase = (size_t)b * NCH * GKS + (size_t)g * NK + lane;

    #pragma unroll 3
    for (int c = w; c < NC; c += 8) {         // first 168 channels: knn_x_n
        float pe = sm[S_PE + c * NK + lane];
        float wv = sm[S_KNNX + lane * 169 + c];
        out[obase + (size_t)c * GKS] = (wv + pe) * pe;
    }
    #pragma unroll 3
    for (int c = NC + w; c < NCH; c += 8) {   // last 168: tiled 7-ch embedding
        float pe = sm[S_PE + c * NK + lane];
        float wv = sm[S_EMB + ((c - NC) % 7) * NK + lane];
        out[obase + (size_t)c * GKS] = (wv + pe) * pe;
    }
}

// ---------------------------------------------------------------------------
extern "C" void kernel_launch(void* const* d_in, const int* in_sizes, int n_in,
                              void* d_out, int out_size) {
    const float* lc_xyz  = (const float*)d_in[0];
    const float* lc_x    = (const float*)d_in[1];
    const float* knn_xyz = (const float*)d_in[2];
    const float* knn_x   = (const float*)d_in[3];
    float* out = (float*)d_out;

    cudaFuncSetAttribute(k_main, cudaFuncAttributeMaxDynamicSharedMemorySize,
                         SMEM_BYTES);

    k_zero<<<1, 32>>>();
    k_reduce_x<<<2048, 256>>>((const float4*)knn_x, lc_x);
    k_reduce_xyz<<<512, 256>>>(knn_xyz, lc_xyz);
    k_finalize<<<1, 1>>>();
    k_main<<<NB * NG, 256, SMEM_BYTES>>>(lc_xyz, lc_x, knn_xyz, knn_x, out);
}

// round 2
// speedup vs baseline: 1.1111x; 1.1111x over previous
#include <cuda_runtime.h>
#include <math.h>

// Problem dims (fixed by setup_inputs)
#define NB   8
#define NG   1024
#define NK   32
#define NC   168
#define NFD  56
#define NCH  336
#define GKS  (NG * NK)     // 32768

#define GRID_R 2048

// Per-block partials: [sx, sx2, sz, sz2]; last-block finalize pattern.
__device__ double       g_part[GRID_R][4];
__device__ unsigned int g_cnt = 0;
__device__ float        g_inv[2];   // [0]=1/(std_x+eps), [1]=1/(std_xyz+eps)

// ---------------------------------------------------------------------------
// Precise fast sincos: Cody-Waite reduction by 2*pi, then MUFU sin/cos.
// ---------------------------------------------------------------------------
namespace cw {
constexpr double TWO_PI_D = 6.283185307179586476925286766559;
constexpr float  RED_A = 6.28125f;                                       // exact
constexpr float  RED_B = (float)(TWO_PI_D - (double)RED_A);
constexpr float  RED_C = (float)(TWO_PI_D - (double)RED_A - (double)RED_B);
constexpr float  INV_2PI = 0.15915494309189535f;
}

__device__ __forceinline__ void fsincos(float x, float& s, float& c) {
    float n = rintf(x * cw::INV_2PI);
    float y = fmaf(n, -cw::RED_A, x);
    y = fmaf(n, -cw::RED_B, y);
    y = fmaf(n, -cw::RED_C, y);
    s = __sinf(y);
    c = __cosf(y);
}

// log2(1000)/56
constexpr float K_LOG2A_FD = 0.17796043365468013f;

// ---------------------------------------------------------------------------
// Fused reduction kernel: knn_x and knn_xyz sums + last-block finalize.
// ---------------------------------------------------------------------------
__device__ __forceinline__ void warp_reduce4(double& a, double& b,
                                             double& c, double& d) {
    #pragma unroll
    for (int o = 16; o; o >>= 1) {
        a += __shfl_down_sync(0xffffffffu, a, o);
        b += __shfl_down_sync(0xffffffffu, b, o);
        c += __shfl_down_sync(0xffffffffu, c, o);
        d += __shfl_down_sync(0xffffffffu, d, o);
    }
}

__global__ __launch_bounds__(256)
void k_reduce(const float4* __restrict__ knn_x4,
              const float*  __restrict__ lc_x,
              const float*  __restrict__ knn_xyz,
              const float*  __restrict__ lc_xyz) {
    const int t = threadIdx.x;
    const int gid = blockIdx.x * 256 + t;
    const int stride = GRID_R * 256;

    // ---- knn_x: d = knn_x - lc_x, accumulate sum, sumsq ----
    float sx = 0.0f, sx2 = 0.0f;
    const int N4 = NB * NG * NK * NC / 4;   // 11,010,048
    for (int i = gid; i < N4; i += stride) {
        int e  = i * 4;
        int bg = e / (NK * NC);
        int c  = e % NC;                    // c % 4 == 0, within one row
        float4 v = __ldcs(&knn_x4[i]);
        float4 l = *(const float4*)(lc_x + bg * NC + c);
        float d0 = v.x - l.x, d1 = v.y - l.y, d2 = v.z - l.z, d3 = v.w - l.w;
        sx  += (d0 + d1) + (d2 + d3);
        sx2 += (d0 * d0 + d1 * d1) + (d2 * d2 + d3 * d3);
    }

    // ---- knn_xyz ----
    float sz = 0.0f, sz2 = 0.0f;
    const int NZ = NB * NG * NK * 3;        // 786,432
    for (int i = gid; i < NZ; i += stride) {
        int d  = i % 3;
        int bg = i / (NK * 3);
        float v = knn_xyz[i] - __ldg(lc_xyz + bg * 3 + d);
        sz  += v;
        sz2 += v * v;
    }

    // ---- block reduce (double) ----
    double a = sx, b = sx2, c = sz, d = sz2;
    warp_reduce4(a, b, c, d);
    __shared__ double sh[8][4];
    int w = t >> 5;
    if ((t & 31) == 0) { sh[w][0] = a; sh[w][1] = b; sh[w][2] = c; sh[w][3] = d; }
    __syncthreads();
    if (t == 0) {
        double r0 = 0, r1 = 0, r2 = 0, r3 = 0;
        #pragma unroll
        for (int i = 0; i < 8; i++) {
            r0 += sh[i][0]; r1 += sh[i][1]; r2 += sh[i][2]; r3 += sh[i][3];
        }
        g_part[blockIdx.x][0] = r0; g_part[blockIdx.x][1] = r1;
        g_part[blockIdx.x][2] = r2; g_part[blockIdx.x][3] = r3;
    }
    __threadfence();

    // ---- last-block finalize ----
    __shared__ int is_last;
    if (t == 0) is_last = (atomicAdd(&g_cnt, 1u) == GRID_R - 1) ? 1 : 0;
    __syncthreads();
    if (!is_last) return;

    double a2 = 0, b2 = 0, c2 = 0, d2 = 0;
    for (int i = t; i < GRID_R; i += 256) {
        a2 += g_part[i][0]; b2 += g_part[i][1];
        c2 += g_part[i][2]; d2 += g_part[i][3];
    }
    warp_reduce4(a2, b2, c2, d2);
    if ((t & 31) == 0) { sh[w][0] = a2; sh[w][1] = b2; sh[w][2] = c2; sh[w][3] = d2; }
    __syncthreads();
    if (t == 0) {
        double r0 = 0, r1 = 0, r2 = 0, r3 = 0;
        #pragma unroll
        for (int i = 0; i < 8; i++) {
            r0 += sh[i][0]; r1 += sh[i][1]; r2 += sh[i][2]; r3 += sh[i][3];
        }
        const double nx = (double)NB * NG * NK * NC;
        const double nz = (double)NB * NG * NK * 3;
        double vx = (r1 - r0 * r0 / nx) / (nx - 1.0);
        double vz = (r3 - r2 * r2 / nz) / (nz - 1.0);
        g_inv[0] = (float)(1.0 / (sqrt(vx) + 1e-5));
        g_inv[1] = (float)(1.0 / (sqrt(vz) + 1e-5));
        g_cnt = 0;                           // reset for next graph replay
    }
}

// ---------------------------------------------------------------------------
// Main kernel: one block per (b,g). 512 threads, 3 blocks/SM (48 warps/SM).
// smem layout (floats):
//   s_pe   [336*32] : pe[c][k]
//   s_knnx [32*169] : normalized knn_x tile, padded row stride 169
//   s_xn   [3*32]   : normalized knn_xyz, [dim][k]
//   s_emb  [7*32]   : {xyz_n(3), cross(3), dot} per k
//   s_lct  [336]    : lc-side trig per channel
//   s_inv  [56]     : 1/alpha^(f/56)
// ---------------------------------------------------------------------------
#define S_PE    0
#define S_KNNX  (S_PE + NCH * NK)            // 10752
#define S_XN    (S_KNNX + NK * 169)          // 16160
#define S_EMB   (S_XN + 3 * NK)              // 16256
#define S_LCT   (S_EMB + 7 * NK)             // 16480
#define S_INV   (S_LCT + NCH)                // 16816
#define SMEM_FLOATS (S_INV + NFD)            // 16872
#define SMEM_BYTES  (SMEM_FLOATS * 4)        // 67488

__global__ __launch_bounds__(512, 3)
void k_main(const float* __restrict__ lc_xyz, const float* __restrict__ lc_x,
            const float* __restrict__ knn_xyz, const float* __restrict__ knn_x,
            float* __restrict__ out) {
    extern __shared__ float sm[];
    const int bg   = blockIdx.x;             // b*NG + g
    const int t    = threadIdx.x;
    const int lane = t & 31;
    const int w    = t >> 5;

    const float inv_x = g_inv[0];
    const float inv_z = g_inv[1];

    // ---- phase 1 -----------------------------------------------------------
    if (t < NFD)
        sm[S_INV + t] = 1.0f / exp2f((float)t * K_LOG2A_FD);

    if (t < 3 * NK) {                         // normalized knn_xyz
        int d = t % 3, k = t / 3;
        float v = knn_xyz[bg * (NK * 3) + t] - __ldg(lc_xyz + bg * 3 + d);
        sm[S_XN + d * NK + k] = v * inv_z;
    }

    if (t < 3 * NFD) {                        // lc-side trig (raw lc_xyz)
        int d = t / NFD, f = t % NFD;
        float inv = 1.0f / exp2f((float)f * K_LOG2A_FD);
        float a = 100.0f * __ldg(lc_xyz + bg * 3 + d) * inv;
        float sn, cs;
        fsincos(a, sn, cs);
        sm[S_LCT + d * 112 + f]      = sn;
        sm[S_LCT + d * 112 + 56 + f] = cs;
    }

    // normalized knn_x tile (coalesced float4 streaming loads, padded rows)
    {
        const float4* kx4 = (const float4*)(knn_x + (size_t)bg * NK * NC);
        for (int i = t; i < NK * NC / 4; i += 512) {
            int e = i * 4;
            int k = e / NC, c = e - k * NC;   // c % 4 == 0
            float4 v = __ldcs(&kx4[i]);
            float4 l = *(const float4*)(lc_x + bg * NC + c);
            float* dst = &sm[S_KNNX + k * 169 + c];
            dst[0] = (v.x - l.x) * inv_x;
            dst[1] = (v.y - l.y) * inv_x;
            dst[2] = (v.z - l.z) * inv_x;
            dst[3] = (v.w - l.w) * inv_x;
        }
    }
    __syncthreads();

    // ---- phase 2 -----------------------------------------------------------
    if (t < NK) {                             // 7-channel geometric embedding
        int k = t;
        float a0 = sm[S_XN + k], a1 = sm[S_XN + NK + k], a2 = sm[S_XN + 2 * NK + k];
        float b0 = __ldg(lc_xyz + bg * 3 + 0);
        float b1 = __ldg(lc_xyz + bg * 3 + 1);
        float b2 = __ldg(lc_xyz + bg * 3 + 2);
        sm[S_EMB + 0 * NK + k] = a0;
        sm[S_EMB + 1 * NK + k] = a1;
        sm[S_EMB + 2 * NK + k] = a2;
        sm[S_EMB + 3 * NK + k] = a1 * b2 - a2 * b1;
        sm[S_EMB + 4 * NK + k] = a2 * b0 - a0 * b2;
        sm[S_EMB + 5 * NK + k] = a0 * b1 - a1 * b0;
        sm[S_EMB + 6 * NK + k] = a0 * b0 + a1 * b1 + a2 * b2;
    }

    // pe fill: 3*56*32 = 5376 sincos tasks; k = t&31 fixed, (d,f) warp-uniform
    for (int task = t; task < 3 * NFD * NK; task += 512) {
        int k  = task & 31;
        int df = task >> 5;                   // warp-uniform
        int d  = df / NFD;
        int f  = df - d * NFD;
        float a = 100.0f * sm[S_XN + d * NK + k] * sm[S_INV + f];
        float sn, cs;
        fsincos(a, sn, cs);
        int cb = d * 112 + f;
        sm[S_PE + cb * NK + k]        = sn + sm[S_LCT + cb];
        sm[S_PE + (cb + 56) * NK + k] = cs + sm[S_LCT + cb + 56];
    }
    __syncthreads();

    // ---- phase 3: write output (streaming stores, 128B per warp-iter) -----
    const int b = bg >> 10;                   // bg / NG
    const int g = bg & (NG - 1);
    const size_t obase = (size_t)b * NCH * GKS + (size_t)g * NK + lane;

    for (int c = w; c < NC; c += 16) {        // first 168 channels: knn_x_n
        float pe = sm[S_PE + c * NK + lane];
        float wv = sm[S_KNNX + lane * 169 + c];
        __stcs(&out[obase + (size_t)c * GKS], (wv + pe) * pe);
    }
    for (int c = NC + w; c < NCH; c += 16) {  // last 168: tiled 7-ch embedding
        float pe = sm[S_PE + c * NK + lane];
        float wv = sm[S_EMB + ((c - NC) % 7) * NK + lane];
        __stcs(&out[obase + (size_t)c * GKS], (wv + pe) * pe);
    }
}

// ---------------------------------------------------------------------------
extern "C" void kernel_launch(void* const* d_in, const int* in_sizes, int n_in,
                              void* d_out, int out_size) {
    const float* lc_xyz  = (const float*)d_in[0];
    const float* lc_x    = (const float*)d_in[1];
    const float* knn_xyz = (const float*)d_in[2];
    const float* knn_x   = (const float*)d_in[3];
    float* out = (float*)d_out;

    cudaFuncSetAttribute(k_main, cudaFuncAttributeMaxDynamicSharedMemorySize,
                         SMEM_BYTES);

    k_reduce<<<GRID_R, 256>>>((const float4*)knn_x, lc_x, knn_xyz, lc_xyz);
    k_main<<<NB * NG, 512, SMEM_BYTES>>>(lc_xyz, lc_x, knn_xyz, knn_x, out);
}

// round 5
// speedup vs baseline: 1.1119x; 1.0007x over previous
#include <cuda_runtime.h>
#include <math.h>

// Problem dims (fixed by setup_inputs)
#define NB   8
#define NG   1024
#define NK   32
#define NC   168
#define NFD  56
#define NCH  336
#define GKS  (NG * NK)     // 32768

#define GRID_R 2048

// Per-block partials: [sx, sx2, sz, sz2]; last-block finalize pattern.
__device__ double       g_part[GRID_R][4];
__device__ unsigned int g_cnt = 0;
__device__ float        g_inv[2];   // [0]=1/(std_x+eps), [1]=1/(std_xyz+eps)

// ---------------------------------------------------------------------------
// Precise fast sincos: Cody-Waite reduction by 2*pi, then MUFU sin/cos.
// ---------------------------------------------------------------------------
namespace cw {
constexpr double TWO_PI_D = 6.283185307179586476925286766559;
constexpr float  RED_A = 6.28125f;                                       // exact
constexpr float  RED_B = (float)(TWO_PI_D - (double)RED_A);
constexpr float  RED_C = (float)(TWO_PI_D - (double)RED_A - (double)RED_B);
constexpr float  INV_2PI = 0.15915494309189535f;
}

__device__ __forceinline__ void fsincos(float x, float& s, float& c) {
    float n = rintf(x * cw::INV_2PI);
    float y = fmaf(n, -cw::RED_A, x);
    y = fmaf(n, -cw::RED_B, y);
    y = fmaf(n, -cw::RED_C, y);
    s = __sinf(y);
    c = __cosf(y);
}

// log2(1000)/56
constexpr float K_LOG2A_FD = 0.17796043365468013f;

// ---------------------------------------------------------------------------
// Fused reduction kernel
// ---------------------------------------------------------------------------
__device__ __forceinline__ void warp_reduce4(double& a, double& b,
                                             double& c, double& d) {
    #pragma unroll
    for (int o = 16; o; o >>= 1) {
        a += __shfl_down_sync(0xffffffffu, a, o);
        b += __shfl_down_sync(0xffffffffu, b, o);
        c += __shfl_down_sync(0xffffffffu, c, o);
        d += __shfl_down_sync(0xffffffffu, d, o);
    }
}

__global__ __launch_bounds__(256)
void k_reduce(const float4* __restrict__ knn_x4,
              const float*  __restrict__ lc_x,
              const float*  __restrict__ knn_xyz,
              const float*  __restrict__ lc_xyz) {
    const int t = threadIdx.x;
    const int gid = blockIdx.x * 256 + t;
    const int stride = GRID_R * 256;

    float sx = 0.0f, sx2 = 0.0f;
    const int N4 = NB * NG * NK * NC / 4;   // 11,010,048
    #pragma unroll 4
    for (int i = gid; i < N4; i += stride) {
        int e  = i * 4;
        int bg = e / (NK * NC);
        int c  = e % NC;                    // c % 4 == 0, within one row
        float4 v = __ldcs(&knn_x4[i]);
        float4 l = *(const float4*)(lc_x + bg * NC + c);
        float d0 = v.x - l.x, d1 = v.y - l.y, d2 = v.z - l.z, d3 = v.w - l.w;
        sx  += (d0 + d1) + (d2 + d3);
        sx2 += (d0 * d0 + d1 * d1) + (d2 * d2 + d3 * d3);
    }

    float sz = 0.0f, sz2 = 0.0f;
    const int NZ = NB * NG * NK * 3;        // 786,432
    #pragma unroll 2
    for (int i = gid; i < NZ; i += stride) {
        int d  = i % 3;
        int bg = i / (NK * 3);
        float v = knn_xyz[i] - __ldg(lc_xyz + bg * 3 + d);
        sz  += v;
        sz2 += v * v;
    }

    double a = sx, b = sx2, c = sz, d = sz2;
    warp_reduce4(a, b, c, d);
    __shared__ double sh[8][4];
    int w = t >> 5;
    if ((t & 31) == 0) { sh[w][0] = a; sh[w][1] = b; sh[w][2] = c; sh[w][3] = d; }
    __syncthreads();
    if (t == 0) {
        double r0 = 0, r1 = 0, r2 = 0, r3 = 0;
        #pragma unroll
        for (int i = 0; i < 8; i++) {
            r0 += sh[i][0]; r1 += sh[i][1]; r2 += sh[i][2]; r3 += sh[i][3];
        }
        g_part[blockIdx.x][0] = r0; g_part[blockIdx.x][1] = r1;
        g_part[blockIdx.x][2] = r2; g_part[blockIdx.x][3] = r3;
    }
    __threadfence();

    __shared__ int is_last;
    if (t == 0) is_last = (atomicAdd(&g_cnt, 1u) == GRID_R - 1) ? 1 : 0;
    __syncthreads();
    if (!is_last) return;

    double a2 = 0, b2 = 0, c2 = 0, d2 = 0;
    for (int i = t; i < GRID_R; i += 256) {
        a2 += g_part[i][0]; b2 += g_part[i][1];
        c2 += g_part[i][2]; d2 += g_part[i][3];
    }
    warp_reduce4(a2, b2, c2, d2);
    if ((t & 31) == 0) { sh[w][0] = a2; sh[w][1] = b2; sh[w][2] = c2; sh[w][3] = d2; }
    __syncthreads();
    if (t == 0) {
        double r0 = 0, r1 = 0, r2 = 0, r3 = 0;
        #pragma unroll
        for (int i = 0; i < 8; i++) {
            r0 += sh[i][0]; r1 += sh[i][1]; r2 += sh[i][2]; r3 += sh[i][3];
        }
        const double nx = (double)NB * NG * NK * NC;
        const double nz = (double)NB * NG * NK * 3;
        double vx = (r1 - r0 * r0 / nx) / (nx - 1.0);
        double vz = (r3 - r2 * r2 / nz) / (nz - 1.0);
        g_inv[0] = (float)(1.0 / (sqrt(vx) + 1e-5));
        g_inv[1] = (float)(1.0 / (sqrt(vz) + 1e-5));
        g_cnt = 0;                           // reset for next graph replay
    }
}

// ---------------------------------------------------------------------------
// Main kernel: one block per (b,g). 512 threads, 3 blocks/SM.
// smem layout (floats):
//   s_pe  [336][32]       : pe[c][k]
//   s_w   [168][36 pad]   : normalized knn_x, channel-major (16B-aligned rows)
//   s_xn  [3][32]         : normalized knn_xyz
//   s_emb [7][32]         : {xyz_n(3), cross(3), dot}
//   s_lct [336]           : lc-side trig
//   s_inv [56]            : 1/alpha^(f/56)
//   s_tab [336]           : per-channel smem float-index of wv row (int bits)
// ---------------------------------------------------------------------------
#define S_PE    0
#define S_W     (S_PE + NCH * NK)            // 10752
#define S_XN    (S_W + NC * 36)              // 16800
#define S_EMB   (S_XN + 3 * NK)              // 16896
#define S_LCT   (S_EMB + 7 * NK)             // 17120
#define S_INV   (S_LCT + NCH)                // 17456
#define S_TAB   (S_INV + NFD)                // 17512
#define SMEM_FLOATS (S_TAB + NCH)            // 17848
#define SMEM_BYTES  (SMEM_FLOATS * 4)        // 71392

__global__ __launch_bounds__(512, 3)
void k_main(const float* __restrict__ lc_xyz, const float* __restrict__ lc_x,
            const float* __restrict__ knn_xyz, const float* __restrict__ knn_x,
            float* __restrict__ out) {
    extern __shared__ float sm[];
    const int bg   = blockIdx.x;             // b*NG + g
    const int t    = threadIdx.x;
    const int lane = t & 31;

    const float inv_x = g_inv[0];
    const float inv_z = g_inv[1];

    // ---- phase 1 -----------------------------------------------------------
    if (t < NFD)
        sm[S_INV + t] = 1.0f / exp2f((float)t * K_LOG2A_FD);

    if (t < 3 * NK) {                         // normalized knn_xyz [d][k]
        int d = t % 3, k = t / 3;
        float v = knn_xyz[bg * (NK * 3) + t] - __ldg(lc_xyz + bg * 3 + d);
        sm[S_XN + d * NK + k] = v * inv_z;
    }

    if (t < 3 * NFD) {                        // lc-side trig (raw lc_xyz)
        int d = t / NFD, f = t % NFD;
        float inv = 1.0f / exp2f((float)f * K_LOG2A_FD);
        float a = 100.0f * __ldg(lc_xyz + bg * 3 + d) * inv;
        float sn, cs;
        fsincos(a, sn, cs);
        sm[S_LCT + d * 112 + f]      = sn;
        sm[S_LCT + d * 112 + 56 + f] = cs;
    }

    if (t < NCH) {                            // wv row index table (float bits)
        int idx = (t < NC) ? (S_W + t * 36)
                           : (S_EMB + ((t - NC) % 7) * NK);
        sm[S_TAB + t] = __int_as_float(idx);
    }

    // normalized knn_x -> channel-major s_w[c][k] (float4 streaming loads)
    {
        const float4* kx4 = (const float4*)(knn_x + (size_t)bg * NK * NC);
        const float4* lx4 = (const float4*)(lc_x + (size_t)bg * NC);
        #pragma unroll
        for (int it = 0; it < 3; ++it) {
            int i = t + it * 512;
            if (i < NK * NC / 4) {            // 1344
                int k  = i / 42;              // 42 float4 per k-row
                int c4 = i - k * 42;
                float4 v = __ldcs(&kx4[i]);
                float4 l = lx4[c4];
                int c = c4 * 4;
                sm[S_W + (c + 0) * 36 + k] = (v.x - l.x) * inv_x;
                sm[S_W + (c + 1) * 36 + k] = (v.y - l.y) * inv_x;
                sm[S_W + (c + 2) * 36 + k] = (v.z - l.z) * inv_x;
                sm[S_W + (c + 3) * 36 + k] = (v.w - l.w) * inv_x;
            }
        }
    }
    __syncthreads();

    // ---- phase 2 -----------------------------------------------------------
    if (t < NK) {                             // 7-channel geometric embedding
        int k = t;
        float a0 = sm[S_XN + k], a1 = sm[S_XN + NK + k], a2 = sm[S_XN + 2 * NK + k];
        float b0 = __ldg(lc_xyz + bg * 3 + 0);
        float b1 = __ldg(lc_xyz + bg * 3 + 1);
        float b2 = __ldg(lc_xyz + bg * 3 + 2);
        sm[S_EMB + 0 * NK + k] = a0;
        sm[S_EMB + 1 * NK + k] = a1;
        sm[S_EMB + 2 * NK + k] = a2;
        sm[S_EMB + 3 * NK + k] = a1 * b2 - a2 * b1;
        sm[S_EMB + 4 * NK + k] = a2 * b0 - a0 * b2;
        sm[S_EMB + 5 * NK + k] = a0 * b1 - a1 * b0;
        sm[S_EMB + 6 * NK + k] = a0 * b0 + a1 * b1 + a2 * b2;
    }

    // pe fill: df = (t>>5) + 16*it (warp-uniform), k = lane
    {
        const int dfb = t >> 5;
        #pragma unroll
        for (int it = 0; it < 11; ++it) {
            int df = dfb + it * 16;
            if (df < 3 * NFD) {
                int d = df / NFD;
                int f = df - d * NFD;
                float a = 100.0f * sm[S_XN + d * NK + lane] * sm[S_INV + f];
                float sn, cs;
                fsincos(a, sn, cs);
                int cb = d * 112 + f;
                sm[S_PE + cb * NK + lane]        = sn + sm[S_LCT + cb];
                sm[S_PE + (cb + 56) * NK + lane] = cs + sm[S_LCT + cb + 56];
            }
        }
    }
    __syncthreads();

    // ---- phase 3: vectorized output (float4 per thread) -------------------
    const int b = bg >> 10;
    const int g = bg & (NG - 1);
    float* obase = out + (size_t)b * NCH * GKS + (size_t)g * NK;

    #pragma unroll
    for (int it = 0; it < 6; ++it) {
        int task = t + it * 512;
        if (task < NCH * 8) {                 // 2688
            int kq = (task & 7) * 4;
            int c  = task >> 3;
            float4 pe = *(const float4*)&sm[S_PE + c * NK + kq];
            int wvi = __float_as_int(sm[S_TAB + c]);
            float4 wv = *(const float4*)&sm[wvi + kq];
            float4 r;
            r.x = (wv.x + pe.x) * pe.x;
            r.y = (wv.y + pe.y) * pe.y;
            r.z = (wv.z + pe.z) * pe.z;
            r.w = (wv.w + pe.w) * pe.w;
            __stcs((float4*)(obase + (size_t)c * GKS + kq), r);
        }
    }
}

// ---------------------------------------------------------------------------
extern "C" void kernel_launch(void* const* d_in, const int* in_sizes, int n_in,
                              void* d_out, int out_size) {
    const float* lc_xyz  = (const float*)d_in[0];
    const float* lc_x    = (const float*)d_in[1];
    const float* knn_xyz = (const float*)d_in[2];
    const float* knn_x   = (const float*)d_in[3];
    float* out = (float*)d_out;

    cudaFuncSetAttribute(k_main, cudaFuncAttributeMaxDynamicSharedMemorySize,
                         SMEM_BYTES);

    k_reduce<<<GRID_R, 256>>>((const float4*)knn_x, lc_x, knn_xyz, lc_xyz);
    k_main<<<NB * NG, 512, SMEM_BYTES>>>(lc_xyz, lc_x, knn_xyz, knn_x, out);
}

// round 6
// speedup vs baseline: 1.2655x; 1.1381x over previous
#include <cuda_runtime.h>
#include <math.h>

// Problem dims (fixed by setup_inputs)
#define NB   8
#define NG   1024
#define NK   32
#define NC   168
#define NFD  56
#define NCH  336
#define GKS  (NG * NK)     // 32768

#define GRID_R 2048

// Per-block partials: [sx, sx2, sz, sz2]; last-block finalize pattern.
__device__ double       g_part[GRID_R][4];
__device__ unsigned int g_cnt = 0;
__device__ float        g_inv[2];   // [0]=1/(std_x+eps), [1]=1/(std_xyz+eps)

// ---------------------------------------------------------------------------
// Precise fast sincos: Cody-Waite reduction by 2*pi, then MUFU sin/cos.
// ---------------------------------------------------------------------------
namespace cw {
constexpr double TWO_PI_D = 6.283185307179586476925286766559;
constexpr float  RED_A = 6.28125f;                                       // exact
constexpr float  RED_B = (float)(TWO_PI_D - (double)RED_A);
constexpr float  RED_C = (float)(TWO_PI_D - (double)RED_A - (double)RED_B);
constexpr float  INV_2PI = 0.15915494309189535f;
}

__device__ __forceinline__ void fsincos(float x, float& s, float& c) {
    float n = rintf(x * cw::INV_2PI);
    float y = fmaf(n, -cw::RED_A, x);
    y = fmaf(n, -cw::RED_B, y);
    y = fmaf(n, -cw::RED_C, y);
    s = __sinf(y);
    c = __cosf(y);
}

// log2(1000)/56
constexpr float K_LOG2A_FD = 0.17796043365468013f;

// ---------------------------------------------------------------------------
// Fused reduction kernel
// ---------------------------------------------------------------------------
__device__ __forceinline__ void warp_reduce4(double& a, double& b,
                                             double& c, double& d) {
    #pragma unroll
    for (int o = 16; o; o >>= 1) {
        a += __shfl_down_sync(0xffffffffu, a, o);
        b += __shfl_down_sync(0xffffffffu, b, o);
        c += __shfl_down_sync(0xffffffffu, c, o);
        d += __shfl_down_sync(0xffffffffu, d, o);
    }
}

__global__ __launch_bounds__(256)
void k_reduce(const float4* __restrict__ knn_x4,
              const float*  __restrict__ lc_x,
              const float*  __restrict__ knn_xyz,
              const float*  __restrict__ lc_xyz) {
    const int t = threadIdx.x;
    const int gid = blockIdx.x * 256 + t;
    const int stride = GRID_R * 256;

    float sx = 0.0f, sx2 = 0.0f;
    const int N4 = NB * NG * NK * NC / 4;   // 11,010,048
    #pragma unroll 8
    for (int i = gid; i < N4; i += stride) {
        int e  = i * 4;
        int bg = e / (NK * NC);
        int c  = e % NC;                    // c % 4 == 0, within one row
        float4 v = __ldcs(&knn_x4[i]);
        float4 l = *(const float4*)(lc_x + bg * NC + c);
        float d0 = v.x - l.x, d1 = v.y - l.y, d2 = v.z - l.z, d3 = v.w - l.w;
        sx  += (d0 + d1) + (d2 + d3);
        sx2 += (d0 * d0 + d1 * d1) + (d2 * d2 + d3 * d3);
    }

    float sz = 0.0f, sz2 = 0.0f;
    const int NZ = NB * NG * NK * 3;        // 786,432
    #pragma unroll 2
    for (int i = gid; i < NZ; i += stride) {
        int d  = i % 3;
        int bg = i / (NK * 3);
        float v = knn_xyz[i] - __ldg(lc_xyz + bg * 3 + d);
        sz  += v;
        sz2 += v * v;
    }

    double a = sx, b = sx2, c = sz, d = sz2;
    warp_reduce4(a, b, c, d);
    __shared__ double sh[8][4];
    int w = t >> 5;
    if ((t & 31) == 0) { sh[w][0] = a; sh[w][1] = b; sh[w][2] = c; sh[w][3] = d; }
    __syncthreads();
    if (t == 0) {
        double r0 = 0, r1 = 0, r2 = 0, r3 = 0;
        #pragma unroll
        for (int i = 0; i < 8; i++) {
            r0 += sh[i][0]; r1 += sh[i][1]; r2 += sh[i][2]; r3 += sh[i][3];
        }
        g_part[blockIdx.x][0] = r0; g_part[blockIdx.x][1] = r1;
        g_part[blockIdx.x][2] = r2; g_part[blockIdx.x][3] = r3;
    }
    __threadfence();

    __shared__ int is_last;
    if (t == 0) is_last = (atomicAdd(&g_cnt, 1u) == GRID_R - 1) ? 1 : 0;
    __syncthreads();
    if (!is_last) return;

    double a2 = 0, b2 = 0, c2 = 0, d2 = 0;
    for (int i = t; i < GRID_R; i += 256) {
        a2 += g_part[i][0]; b2 += g_part[i][1];
        c2 += g_part[i][2]; d2 += g_part[i][3];
    }
    warp_reduce4(a2, b2, c2, d2);
    if ((t & 31) == 0) { sh[w][0] = a2; sh[w][1] = b2; sh[w][2] = c2; sh[w][3] = d2; }
    __syncthreads();
    if (t == 0) {
        double r0 = 0, r1 = 0, r2 = 0, r3 = 0;
        #pragma unroll
        for (int i = 0; i < 8; i++) {
            r0 += sh[i][0]; r1 += sh[i][1]; r2 += sh[i][2]; r3 += sh[i][3];
        }
        const double nx = (double)NB * NG * NK * NC;
        const double nz = (double)NB * NG * NK * 3;
        double vx = (r1 - r0 * r0 / nx) / (nx - 1.0);
        double vz = (r3 - r2 * r2 / nz) / (nz - 1.0);
        g_inv[0] = (float)(1.0 / (sqrt(vx) + 1e-5));
        g_inv[1] = (float)(1.0 / (sqrt(vz) + 1e-5));
        g_cnt = 0;                           // reset for next graph replay
    }
}

// ---------------------------------------------------------------------------
// Main kernel: one block per (b,g). 256 threads, ~24KB smem, 8 blocks/SM.
// Fused: trig loop writes output directly (no pe staging array).
// smem (floats):
//   s_w   [32][169] : normalized knn_x, k-major, stride 169 (169%32=9, gcd=1)
//   s_xn  [3][32]   : normalized knn_xyz [d][k]
//   s_emb [7][32]   : {xyz_n(3), cross(3), dot}
//   s_lct [336]     : lc-side trig per channel
//   s_inv [56]      : 1/alpha^(f/56)
// ---------------------------------------------------------------------------
#define S_W     0
#define S_XN    (S_W + NK * 169)             // 5408
#define S_EMB   (S_XN + 3 * NK)              // 5504
#define S_LCT   (S_EMB + 7 * NK)             // 5728
#define S_INV   (S_LCT + NCH)                // 6064
#define SMEM_FLOATS (S_INV + NFD)            // 6120  (~24.5 KB)

__global__ __launch_bounds__(256, 8)
void k_main(const float* __restrict__ lc_xyz, const float* __restrict__ lc_x,
            const float* __restrict__ knn_xyz, const float* __restrict__ knn_x,
            float* __restrict__ out) {
    __shared__ float sm[SMEM_FLOATS];
    const int bg   = blockIdx.x;             // b*NG + g
    const int t    = threadIdx.x;
    const int lane = t & 31;

    const float inv_x = g_inv[0];
    const float inv_z = g_inv[1];

    // ---- phase 1: stage everything into smem -------------------------------
    if (t < NFD)
        sm[S_INV + t] = 1.0f / exp2f((float)t * K_LOG2A_FD);

    if (t < 3 * NK) {                         // normalized knn_xyz [d][k]
        int d = t % 3, k = t / 3;
        float v = knn_xyz[bg * (NK * 3) + t] - __ldg(lc_xyz + bg * 3 + d);
        sm[S_XN + d * NK + k] = v * inv_z;
    }

    if (t < 3 * NFD) {                        // lc-side trig (raw lc_xyz)
        int d = t / NFD, f = t % NFD;
        float inv = 1.0f / exp2f((float)f * K_LOG2A_FD);
        float a = 100.0f * __ldg(lc_xyz + bg * 3 + d) * inv;
        float sn, cs;
        fsincos(a, sn, cs);
        sm[S_LCT + d * 112 + f]      = sn;
        sm[S_LCT + d * 112 + 56 + f] = cs;
    }

    // normalized knn_x -> s_w[k][169] (coalesced float4 streaming loads)
    {
        const float4* kx4 = (const float4*)(knn_x + (size_t)bg * NK * NC);
        const float4* lx4 = (const float4*)(lc_x + (size_t)bg * NC);
        #pragma unroll
        for (int it = 0; it < 6; ++it) {
            int i = t + it * 256;
            if (i < NK * NC / 4) {            // 1344
                int k  = i / 42;              // 42 float4 per k-row
                int c4 = i - k * 42;
                float4 v = __ldcs(&kx4[i]);
                float4 l = lx4[c4];
                float* dst = &sm[S_W + k * 169 + c4 * 4];
                dst[0] = (v.x - l.x) * inv_x;
                dst[1] = (v.y - l.y) * inv_x;
                dst[2] = (v.z - l.z) * inv_x;
                dst[3] = (v.w - l.w) * inv_x;
            }
        }
    }
    __syncthreads();

    // ---- phase 2: 7-channel geometric embedding ----------------------------
    if (t < NK) {
        int k = t;
        float a0 = sm[S_XN + k], a1 = sm[S_XN + NK + k], a2 = sm[S_XN + 2 * NK + k];
        float b0 = __ldg(lc_xyz + bg * 3 + 0);
        float b1 = __ldg(lc_xyz + bg * 3 + 1);
        float b2 = __ldg(lc_xyz + bg * 3 + 2);
        sm[S_EMB + 0 * NK + k] = a0;
        sm[S_EMB + 1 * NK + k] = a1;
        sm[S_EMB + 2 * NK + k] = a2;
        sm[S_EMB + 3 * NK + k] = a1 * b2 - a2 * b1;
        sm[S_EMB + 4 * NK + k] = a2 * b0 - a0 * b2;
        sm[S_EMB + 5 * NK + k] = a0 * b1 - a1 * b0;
        sm[S_EMB + 6 * NK + k] = a0 * b0 + a1 * b1 + a2 * b2;
    }
    __syncthreads();

    // ---- phase 3: fused trig + output --------------------------------------
    // 5376 tasks = 21 * 256; task k = lane (fixed), df warp-uniform.
    // Each task emits 2 output channels: cb = d*112+f (sin), cb+56 (cos).
    const int b = bg >> 10;
    const int g = bg & (NG - 1);
    float* obase = out + (size_t)b * NCH * GKS + (size_t)g * NK + lane;

    const int dfb = t >> 5;                   // 0..7
    #pragma unroll 3
    for (int it = 0; it < 21; ++it) {
        int df = dfb + it * 8;                // 0..167, warp-uniform
        int d  = df / NFD;
        int f  = df - d * NFD;
        float a = 100.0f * sm[S_XN + d * NK + lane] * sm[S_INV + f];
        float sn, cs;
        fsincos(a, sn, cs);
        int cb1 = d * 112 + f;
        int cb2 = cb1 + 56;
        float pe1 = sn + sm[S_LCT + cb1];
        float pe2 = cs + sm[S_LCT + cb2];
        float wv1 = (cb1 < NC) ? sm[S_W + lane * 169 + cb1]
                               : sm[S_EMB + ((cb1 - NC) % 7) * NK + lane];
        float wv2 = (cb2 < NC) ? sm[S_W + lane * 169 + cb2]
                               : sm[S_EMB + ((cb2 - NC) % 7) * NK + lane];
        __stcs(obase + (size_t)cb1 * GKS, (wv1 + pe1) * pe1);
        __stcs(obase + (size_t)cb2 * GKS, (wv2 + pe2) * pe2);
    }
}

// ---------------------------------------------------------------------------
extern "C" void kernel_launch(void* const* d_in, const int* in_sizes, int n_in,
                              void* d_out, int out_size) {
    const float* lc_xyz  = (const float*)d_in[0];
    const float* lc_x    = (const float*)d_in[1];
    const float* knn_xyz = (const float*)d_in[2];
    const float* knn_x   = (const float*)d_in[3];
    float* out = (float*)d_out;

    k_reduce<<<GRID_R, 256>>>((const float4*)knn_x, lc_x, knn_xyz, lc_xyz);
    k_main<<<NB * NG, 256>>>(lc_xyz, lc_x, knn_xyz, knn_x, out);
}

// round 10
// speedup vs baseline: 1.6115x; 1.2734x over previous
#include <cuda_runtime.h>
#include <math.h>

// Problem dims (fixed by setup_inputs)
#define NB   8
#define NG   1024
#define NK   32
#define NC   168
#define NFD  56
#define NCH  336
#define GKS  (NG * NK)     // 32768

#define GRID_R 2048

// Per-block partials: [sx, sx2, sz, sz2]; last-block finalize pattern.
__device__ double       g_part[GRID_R][4];
__device__ unsigned int g_cnt = 0;
__device__ float        g_inv[2];   // [0]=1/(std_x+eps), [1]=1/(std_xyz+eps)

// ---------------------------------------------------------------------------
// Precise fast sincos: Cody-Waite reduction by 2*pi, then MUFU sin/cos.
// ---------------------------------------------------------------------------
namespace cw {
constexpr double TWO_PI_D = 6.283185307179586476925286766559;
constexpr float  RED_A = 6.28125f;                                       // exact
constexpr float  RED_B = (float)(TWO_PI_D - (double)RED_A);
constexpr float  RED_C = (float)(TWO_PI_D - (double)RED_A - (double)RED_B);
constexpr float  INV_2PI = 0.15915494309189535f;
}

__device__ __forceinline__ void fsincos(float x, float& s, float& c) {
    float n = rintf(x * cw::INV_2PI);
    float y = fmaf(n, -cw::RED_A, x);
    y = fmaf(n, -cw::RED_B, y);
    y = fmaf(n, -cw::RED_C, y);
    s = __sinf(y);
    c = __cosf(y);
}

// log2(1000)/56
constexpr float K_LOG2A_FD = 0.17796043365468013f;

// ---------------------------------------------------------------------------
// Reduction kernel: each block owns 4 contiguous bg rows (86KB chunk).
// ---------------------------------------------------------------------------
__device__ __forceinline__ void warp_reduce4(double& a, double& b,
                                             double& c, double& d) {
    #pragma unroll
    for (int o = 16; o; o >>= 1) {
        a += __shfl_down_sync(0xffffffffu, a, o);
        b += __shfl_down_sync(0xffffffffu, b, o);
        c += __shfl_down_sync(0xffffffffu, c, o);
        d += __shfl_down_sync(0xffffffffu, d, o);
    }
}

__global__ __launch_bounds__(256)
void k_reduce(const float4* __restrict__ knn_x4,
              const float*  __restrict__ lc_x,
              const float*  __restrict__ knn_xyz,
              const float*  __restrict__ lc_xyz) {
    const int t   = threadIdx.x;
    const int bg0 = blockIdx.x * 4;
    const float4* kx4 = knn_x4 + (size_t)bg0 * 1344;   // 4 rows * 1344 float4

    __shared__ float4 slc[168];                         // 4 lc rows (42 each)
    if (t < 168) slc[t] = ((const float4*)lc_x)[bg0 * 42 + t];
    __syncthreads();

    float sx = 0.0f, sx2 = 0.0f;
    #pragma unroll 7
    for (int it = 0; it < 21; ++it) {                   // 21*256 = 5376 exact
        int j = t + it * 256;
        float4 v = __ldcs(&kx4[j]);
        float4 l = slc[(j / 1344) * 42 + j % 42];       // 1344 % 42 == 0
        float d0 = v.x - l.x, d1 = v.y - l.y, d2 = v.z - l.z, d3 = v.w - l.w;
        sx  += (d0 + d1) + (d2 + d3);
        sx2 += (d0 * d0 + d1 * d1) + (d2 * d2 + d3 * d3);
    }

    float sz = 0.0f, sz2 = 0.0f;
    #pragma unroll
    for (int i = t; i < 384; i += 256) {                // 4 bg * 96 xyz floats
        int bgl = i / 96;
        int d   = i % 3;
        float v = knn_xyz[bg0 * 96 + i] - __ldg(lc_xyz + (bg0 + bgl) * 3 + d);
        sz  += v;
        sz2 += v * v;
    }

    double a = sx, b = sx2, c = sz, d = sz2;
    warp_reduce4(a, b, c, d);
    __shared__ double sh[8][4];
    int w = t >> 5;
    if ((t & 31) == 0) { sh[w][0] = a; sh[w][1] = b; sh[w][2] = c; sh[w][3] = d; }
    __syncthreads();
    if (t == 0) {
        double r0 = 0, r1 = 0, r2 = 0, r3 = 0;
        #pragma unroll
        for (int i = 0; i < 8; i++) {
            r0 += sh[i][0]; r1 += sh[i][1]; r2 += sh[i][2]; r3 += sh[i][3];
        }
        g_part[blockIdx.x][0] = r0; g_part[blockIdx.x][1] = r1;
        g_part[blockIdx.x][2] = r2; g_part[blockIdx.x][3] = r3;
    }
    __threadfence();

    __shared__ int is_last;
    if (t == 0) is_last = (atomicAdd(&g_cnt, 1u) == GRID_R - 1) ? 1 : 0;
    __syncthreads();
    if (!is_last) return;

    double a2 = 0, b2 = 0, c2 = 0, d2 = 0;
    for (int i = t; i < GRID_R; i += 256) {
        a2 += g_part[i][0]; b2 += g_part[i][1];
        c2 += g_part[i][2]; d2 += g_part[i][3];
    }
    warp_reduce4(a2, b2, c2, d2);
    if ((t & 31) == 0) { sh[w][0] = a2; sh[w][1] = b2; sh[w][2] = c2; sh[w][3] = d2; }
    __syncthreads();
    if (t == 0) {
        double r0 = 0, r1 = 0, r2 = 0, r3 = 0;
        #pragma unroll
        for (int i = 0; i < 8; i++) {
            r0 += sh[i][0]; r1 += sh[i][1]; r2 += sh[i][2]; r3 += sh[i][3];
        }
        const double nx = (double)NB * NG * NK * NC;
        const double nz = (double)NB * NG * NK * 3;
        double vx = (r1 - r0 * r0 / nx) / (nx - 1.0);
        double vz = (r3 - r2 * r2 / nz) / (nz - 1.0);
        g_inv[0] = (float)(1.0 / (sqrt(vx) + 1e-5));
        g_inv[1] = (float)(1.0 / (sqrt(vz) + 1e-5));
        g_cnt = 0;                           // reset for next graph replay
    }
}

// ---------------------------------------------------------------------------
// Main kernel: one block per (b,g). 256 threads, ~25.4KB smem.
// Phase 3 vectorized: each task = (df, kq) -> 4 sincos, 2 STG.128.
// smem (floats):
//   s_w   [32][177] : cols 0..167 = normalized knn_x (k-major);
//                     cols 169..175 = 7-ch geometric embedding
//                     (stride 177 % 8 == 1 -> conflict-free kq gathers)
//   s_xn  [3][32]   : normalized knn_xyz [d][k]  (16B aligned)
//   s_lct [336]     : lc-side trig per channel
//   s_inv [56]      : 1/alpha^(f/56)
//   s_tab [336]     : per-channel wv column index (int bits)
// ---------------------------------------------------------------------------
#define SW_STRIDE 177
#define S_W     0
#define S_XN    (S_W + NK * SW_STRIDE)       // 5664
#define S_LCT   (S_XN + 3 * NK)              // 5760
#define S_INV   (S_LCT + NCH)                // 6096
#define S_TAB   (S_INV + NFD)                // 6152
#define SMEM_FLOATS (S_TAB + NCH)            // 6488 (~25.4 KB)

__global__ __launch_bounds__(256, 6)
void k_main(const float* __restrict__ lc_xyz, const float* __restrict__ lc_x,
            const float* __restrict__ knn_xyz, const float* __restrict__ knn_x,
            float* __restrict__ out) {
    __shared__ float sm[SMEM_FLOATS];
    const int bg = blockIdx.x;               // b*NG + g
    const int t  = threadIdx.x;

    const float inv_x = g_inv[0];
    const float inv_z = g_inv[1];

    // ---- phase 1: stage into smem ------------------------------------------
    if (t < NFD)
        sm[S_INV + t] = 1.0f / exp2f((float)t * K_LOG2A_FD);

    if (t < 3 * NK) {                         // normalized knn_xyz [d][k]
        int d = t % 3, k = t / 3;
        float v = knn_xyz[bg * (NK * 3) + t] - __ldg(lc_xyz + bg * 3 + d);
        sm[S_XN + d * NK + k] = v * inv_z;
    }

    if (t < 3 * NFD) {                        // lc-side trig (raw lc_xyz)
        int d = t / NFD, f = t % NFD;
        float inv = 1.0f / exp2f((float)f * K_LOG2A_FD);
        float a = 100.0f * __ldg(lc_xyz + bg * 3 + d) * inv;
        float sn, cs;
        fsincos(a, sn, cs);
        sm[S_LCT + d * 112 + f]      = sn;
        sm[S_LCT + d * 112 + 56 + f] = cs;
    }

    // wv column table — FULL 336 entries with a 256-thread block (r8 bugfix)
    for (int i = t; i < NCH; i += 256) {
        int col = (i < NC) ? i : (169 + (i - NC) % 7);
        sm[S_TAB + i] = __int_as_float(col);
    }

    // normalized knn_x -> s_w[k][c], row stride 177
    {
        const float4* kx4 = (const float4*)(knn_x + (size_t)bg * NK * NC);
        const float4* lx4 = (const float4*)(lc_x + (size_t)bg * NC);
        #pragma unroll
        for (int it = 0; it < 6; ++it) {
            int i = t + it * 256;
            if (i < NK * NC / 4) {            // 1344
                int k  = i / 42;
                int c4 = i - k * 42;
                float4 v = __ldcs(&kx4[i]);
                float4 l = lx4[c4];
                float* dst = &sm[S_W + k * SW_STRIDE + c4 * 4];
                dst[0] = (v.x - l.x) * inv_x;
                dst[1] = (v.y - l.y) * inv_x;
                dst[2] = (v.z - l.z) * inv_x;
                dst[3] = (v.w - l.w) * inv_x;
            }
        }
    }
    __syncthreads();

    // ---- phase 2: 7-ch geometric embedding -> s_w cols 169..175 ------------
    if (t < NK) {
        int k = t;
        float a0 = sm[S_XN + k], a1 = sm[S_XN + NK + k], a2 = sm[S_XN + 2 * NK + k];
        float b0 = __ldg(lc_xyz + bg * 3 + 0);
        float b1 = __ldg(lc_xyz + bg * 3 + 1);
        float b2 = __ldg(lc_xyz + bg * 3 + 2);
        float* row = &sm[S_W + k * SW_STRIDE + 169];
        row[0] = a0;
        row[1] = a1;
        row[2] = a2;
        row[3] = a1 * b2 - a2 * b1;
        row[4] = a2 * b0 - a0 * b2;
        row[5] = a0 * b1 - a1 * b0;
        row[6] = a0 * b0 + a1 * b1 + a2 * b2;
    }
    __syncthreads();

    // ---- phase 3: vectorized trig + output ---------------------------------
    // task = (df, kq): 168 * 8 tasks; 4 sincos, 2 float4 stores per task.
    const int b = bg >> 10;
    const int g = bg & (NG - 1);
    float* obase = out + (size_t)b * NCH * GKS + (size_t)g * NK;

    const int kq  = t & 7;
    const int k0  = kq * 4;
    const int df0 = t >> 3;                   // 0..31
    const int wbase = S_W + k0 * SW_STRIDE;

    #pragma unroll
    for (int it = 0; it < 6; ++it) {
        int df = df0 + it * 32;
        if (df < 3 * NFD) {
            int d = df / NFD;
            int f = df - d * NFD;
            float amp = 100.0f * sm[S_INV + f];
            const float4 x = *(const float4*)&sm[S_XN + d * NK + k0];
            float s0, c0, s1, c1, s2, c2, s3, c3;
            fsincos(amp * x.x, s0, c0);
            fsincos(amp * x.y, s1, c1);
            fsincos(amp * x.z, s2, c2);
            fsincos(amp * x.w, s3, c3);
            int cb1 = df + d * 56;            // d*112 + f
            int cb2 = cb1 + 56;
            float l1 = sm[S_LCT + cb1];
            float l2 = sm[S_LCT + cb2];
            int col1 = __float_as_int(sm[S_TAB + cb1]);
            int col2 = __float_as_int(sm[S_TAB + cb2]);
            float4 r1, r2;
            float p;
            p = s0 + l1; r1.x = (sm[wbase + 0 * SW_STRIDE + col1] + p) * p;
            p = s1 + l1; r1.y = (sm[wbase + 1 * SW_STRIDE + col1] + p) * p;
            p = s2 + l1; r1.z = (sm[wbase + 2 * SW_STRIDE + col1] + p) * p;
            p = s3 + l1; r1.w = (sm[wbase + 3 * SW_STRIDE + col1] + p) * p;
            p = c0 + l2; r2.x = (sm[wbase + 0 * SW_STRIDE + col2] + p) * p;
            p = c1 + l2; r2.y = (sm[wbase + 1 * SW_STRIDE + col2] + p) * p;
            p = c2 + l2; r2.z = (sm[wbase + 2 * SW_STRIDE + col2] + p) * p;
            p = c3 + l2; r2.w = (sm[wbase + 3 * SW_STRIDE + col2] + p) * p;
            __stcs((float4*)(obase + (size_t)cb1 * GKS + k0), r1);
            __stcs((float4*)(obase + (size_t)cb2 * GKS + k0), r2);
        }
    }
}

// ---------------------------------------------------------------------------
extern "C" void kernel_launch(void* const* d_in, const int* in_sizes, int n_in,
                              void* d_out, int out_size) {
    const float* lc_xyz  = (const float*)d_in[0];
    const float* lc_x    = (const float*)d_in[1];
    const float* knn_xyz = (const float*)d_in[2];
    const float* knn_x   = (const float*)d_in[3];
    float* out = (float*)d_out;

    k_reduce<<<GRID_R, 256>>>((const float4*)knn_x, lc_x, knn_xyz, lc_xyz);
    k_main<<<NB * NG, 256>>>(lc_xyz, lc_x, knn_xyz, knn_x, out);
}